// round 4
// baseline (speedup 1.0000x reference)
#include <cuda_runtime.h>
#include <cuda_bf16.h>

#define NUM_CLASSES 16384
#define FEAT_DIM    1024
#define ALPHA       0.5f
#define NSLOT       64
#define SLOT_STRIDE 16   // 16 doubles = 128 B -> distinct LTS partitions

// Scratch (zero at process start; last block of the main kernel restores all
// of it to zero every run, so each graph replay starts clean).
__device__ int          g_counts[NUM_CLASSES];
__device__ double       g_partial[NSLOT * SLOT_STRIDE];
__device__ unsigned int g_ticket;

// ---------------------------------------------------------------------------
// Kernel 1: bincount (g_counts is zero at entry)
// ---------------------------------------------------------------------------
__global__ __launch_bounds__(128)
void bincount_kernel(const int* __restrict__ y_true) {
    int idx = blockIdx.x * blockDim.x + threadIdx.x;
    atomicAdd(&g_counts[y_true[idx]], 1);
}

// ---------------------------------------------------------------------------
// Kernel 2: fused main + finalize.
// One block (128 threads) per row; 8 independent LDG.128 per thread.
//   j  = y_true[i], jj = y_true[j]
//   d  = y_pred[i] - centers[j] + (ALPHA/(counts[jj]+1)) * (centers[jj] - y_pred[j])
// Completion protocol: relaxed RED partial -> RELEASE ticket (no L1 flush,
// unlike __threadfence which emits CCTL.IVALL per block — the R2 regression).
// Last block: one acquire fence, reduce, write out, reset scratch.
// ---------------------------------------------------------------------------
__global__ __launch_bounds__(128)
void centerloss_kernel(const int*   __restrict__ y_true,
                       const float* __restrict__ y_pred,
                       const float* __restrict__ centers,
                       float*       __restrict__ out) {
    const int row = blockIdx.x;
    const int tid = threadIdx.x;

    const int j  = y_true[row];
    const int jj = y_true[j];
    const float scale = ALPHA / ((float)g_counts[jj] + 1.0f);

    const float4* yp_i = (const float4*)(y_pred  + (size_t)row * FEAT_DIM);
    const float4* c_j  = (const float4*)(centers + (size_t)j   * FEAT_DIM);
    const float4* c_jj = (const float4*)(centers + (size_t)jj  * FEAT_DIM);
    const float4* yp_j = (const float4*)(y_pred  + (size_t)j   * FEAT_DIM);

    const int t0 = tid;
    const int t1 = tid + 128;

    float4 a0 = yp_i[t0], a1 = yp_i[t1];
    float4 b0 = c_j[t0],  b1 = c_j[t1];
    float4 c0 = c_jj[t0], c1 = c_jj[t1];
    float4 d0 = yp_j[t0], d1 = yp_j[t1];

    float s = 0.0f;
    {
        float dx = a0.x - b0.x + scale * (c0.x - d0.x);
        float dy = a0.y - b0.y + scale * (c0.y - d0.y);
        float dz = a0.z - b0.z + scale * (c0.z - d0.z);
        float dw = a0.w - b0.w + scale * (c0.w - d0.w);
        s += dx*dx + dy*dy + dz*dz + dw*dw;
    }
    {
        float dx = a1.x - b1.x + scale * (c1.x - d1.x);
        float dy = a1.y - b1.y + scale * (c1.y - d1.y);
        float dz = a1.z - b1.z + scale * (c1.z - d1.z);
        float dw = a1.w - b1.w + scale * (c1.w - d1.w);
        s += dx*dx + dy*dy + dz*dz + dw*dw;
    }

    #pragma unroll
    for (int off = 16; off > 0; off >>= 1)
        s += __shfl_xor_sync(0xFFFFFFFFu, s, off);

    __shared__ float warp_sums[4];
    __shared__ bool  s_last;
    const int wid = tid >> 5;
    const int lid = tid & 31;
    if (lid == 0) warp_sums[wid] = s;
    __syncthreads();

    if (tid == 0) {
        float v = warp_sums[0] + warp_sums[1] + warp_sums[2] + warp_sums[3];
        // relaxed partial add (L2 atomic)
        atomicAdd(&g_partial[(row & (NSLOT - 1)) * SLOT_STRIDE], (double)v);
        // RELEASE ticket: orders the partial add before the ticket without an
        // L1-flushing fence.
        unsigned int old;
        asm volatile("atom.add.release.gpu.global.u32 %0, [%1], 1;"
                     : "=r"(old) : "l"(&g_ticket) : "memory");
        s_last = (old == (unsigned int)(gridDim.x - 1));
    }
    __syncthreads();

    if (s_last) {
        // single acquire fence in ONE block (one CCTL.IVALL total)
        asm volatile("fence.acq_rel.gpu;" ::: "memory");

        // reduce 64 partial slots (2 warps hold data)
        double dv = (tid < NSLOT) ? g_partial[tid * SLOT_STRIDE] : 0.0;
        #pragma unroll
        for (int off = 16; off > 0; off >>= 1)
            dv += __shfl_xor_sync(0xFFFFFFFFu, dv, off);
        __shared__ double dsum[2];
        if (wid < 2 && lid == 0) dsum[wid] = dv;
        __syncthreads();
        if (tid == 0) {
            out[0] = (float)((dsum[0] + dsum[1]) /
                             ((double)NUM_CLASSES * (double)FEAT_DIM));
            g_ticket = 0u;
        }

        // reset scratch for the next replay
        if (tid < NSLOT) g_partial[tid * SLOT_STRIDE] = 0.0;
        #pragma unroll 4
        for (int k = tid; k < NUM_CLASSES; k += 128) g_counts[k] = 0;
    }
}

extern "C" void kernel_launch(void* const* d_in, const int* in_sizes, int n_in,
                              void* d_out, int out_size) {
    const int*   y_true  = (const int*)  d_in[0];
    const float* y_pred  = (const float*)d_in[1];
    const float* centers = (const float*)d_in[2];
    float* out = (float*)d_out;

    bincount_kernel<<<NUM_CLASSES / 128, 128>>>(y_true);
    centerloss_kernel<<<NUM_CLASSES, 128>>>(y_true, y_pred, centers, out);
}